// round 7
// baseline (speedup 1.0000x reference)
#include <cuda_runtime.h>
#include <math.h>

#define N_NODES 50000
#define N_EDGES 600000
#define D_IN    128
#define D_H     256

// ---------------- static device scratch (no allocations allowed) ------------
__device__ int   g_is64;          // 1 if edge_index is int64, 0 if int32
__device__ int   g_deg[N_NODES];
__device__ int   g_off[N_NODES + 1];
__device__ int   g_cur[N_NODES];
__device__ int   g_csr[N_EDGES];
__device__ float g_h0[(size_t)N_NODES * D_IN];
__device__ float g_h1[(size_t)N_NODES * D_H];
__device__ float g_h2[(size_t)N_NODES * D_H];
__device__ float g_h3[(size_t)N_NODES * D_H];
__device__ float g_h4[(size_t)N_NODES * D_H];

// ---------------- edge dtype detection --------------------------------------
// Node ids are < 50000, so if the buffer holds little-endian int64 every odd
// 32-bit word is 0. For int32 data those words are random node ids; the odds
// that 128 consecutive odd words are all zero is ~(1/50000)^128 ~ 0.
__global__ void detect_kernel(const int* __restrict__ ei32, int* __restrict__ is64) {
    if (threadIdx.x == 0) {
        int all_zero = 1;
        for (int i = 0; i < 128; i++)
            if (ei32[2 * i + 1] != 0) { all_zero = 0; break; }
        *is64 = all_zero;
    }
}

// edge accessor: works for either dtype given the raw int32 view of the buffer
__device__ __forceinline__ int edge_src(const int* ei32, int is64, int i) {
    return is64 ? ei32[2 * i] : ei32[i];
}
__device__ __forceinline__ int edge_dst(const int* ei32, int is64, int i) {
    return is64 ? ei32[2 * N_EDGES + 2 * i] : ei32[N_EDGES + i];
}

// ---------------- CSR build -------------------------------------------------
__global__ void zero_deg_kernel(int* __restrict__ deg) {
    int i = blockIdx.x * blockDim.x + threadIdx.x;
    if (i < N_NODES) deg[i] = 0;
}

__global__ void hist_kernel(const int* __restrict__ ei32, const int* __restrict__ is64p,
                            int* __restrict__ deg) {
    int i = blockIdx.x * blockDim.x + threadIdx.x;
    if (i < N_EDGES) atomicAdd(&deg[edge_dst(ei32, *is64p, i)], 1);
}

// single block, 1024 threads: exclusive scan of degrees -> offsets + cursors
__global__ void scan_kernel(const int* __restrict__ deg, int* __restrict__ off,
                            int* __restrict__ cur) {
    __shared__ int ssum[1024];
    int tid = threadIdx.x;
    const int CH = (N_NODES + 1023) / 1024;  // 49
    int base = tid * CH;
    int s = 0;
    for (int i = 0; i < CH; i++) {
        int idx = base + i;
        if (idx < N_NODES) s += deg[idx];
    }
    ssum[tid] = s;
    __syncthreads();
    // Hillis-Steele inclusive scan
    for (int d = 1; d < 1024; d <<= 1) {
        int v = 0;
        if (tid >= d) v = ssum[tid - d];
        __syncthreads();
        if (tid >= d) ssum[tid] += v;
        __syncthreads();
    }
    int run = (tid == 0) ? 0 : ssum[tid - 1];
    for (int i = 0; i < CH; i++) {
        int idx = base + i;
        if (idx < N_NODES) {
            off[idx] = run;
            cur[idx] = run;
            run += deg[idx];
        }
    }
    if (tid == 0) off[N_NODES] = ssum[1023];
}

__global__ void fill_kernel(const int* __restrict__ ei32, const int* __restrict__ is64p,
                            int* __restrict__ cur, int* __restrict__ csr) {
    int i = blockIdx.x * blockDim.x + threadIdx.x;
    if (i < N_EDGES) {
        int is64 = *is64p;
        int p = atomicAdd(&cur[edge_dst(ei32, is64, i)], 1);
        csr[p] = edge_src(ei32, is64, i);
    }
}

// ---------------- gather aggregation: out[i] = h[i] + sum_{j->i} h[j] -------
template <int D>
__global__ void gather_kernel(const float* __restrict__ h, const int* __restrict__ csr,
                              const int* __restrict__ off, float* __restrict__ out) {
    int node = blockIdx.x * (blockDim.x / 32) + (threadIdx.x >> 5);
    if (node >= N_NODES) return;
    int lane = threadIdx.x & 31;
    constexpr int V = D / 128;  // float4 per lane: 1 (D=128) or 2 (D=256)

    float4 acc[V];
    const float4* rp = (const float4*)(h + (size_t)node * D);
#pragma unroll
    for (int v = 0; v < V; v++) acc[v] = rp[lane + 32 * v];

    int beg = off[node], end = off[node + 1];
    for (int e = beg; e < end; e++) {
        int s = csr[e];
        const float4* sp = (const float4*)(h + (size_t)s * D);
#pragma unroll
        for (int v = 0; v < V; v++) {
            float4 t = sp[lane + 32 * v];
            acc[v].x += t.x; acc[v].y += t.y; acc[v].z += t.z; acc[v].w += t.w;
        }
    }
    float4* op = (float4*)(out + (size_t)node * D);
#pragma unroll
    for (int v = 0; v < V; v++) op[lane + 32 * v] = acc[v];
}

// ---------------- SGEMM: C[M x 256] = act(A[M x K] @ W[K x 256] + bias) -----
// Block: 64 rows x 128 cols, 256 threads, 8x4 register tile per thread.
// Full W-column-tile [K x 128] and A-tile [64 x K] staged in shared memory.
template <int K, bool RELU>
__global__ void __launch_bounds__(256)
sgemm_kernel(const float* __restrict__ A, const float* __restrict__ W,
             const float* __restrict__ bias, float* __restrict__ C, int M) {
    extern __shared__ float sm[];
    float* ws = sm;            // [K][128]
    float* as = sm + K * 128;  // [64][K]

    int tid = threadIdx.x;
    int rb = blockIdx.x * 64;
    int cb = blockIdx.y * 128;

    // load W tile: K rows x 128 cols (cols cb..cb+127 of the 256-wide matrix)
    for (int i = tid; i < K * 32; i += 256) {
        int k = i >> 5, c4 = i & 31;
        float4 wv = ((const float4*)(W + (size_t)k * 256 + cb))[c4];
        ((float4*)(ws + k * 128))[c4] = wv;
    }
    // load A tile: 64 rows x K (row-clamped for the ragged last block)
    for (int i = tid; i < 64 * (K / 4); i += 256) {
        int r = i / (K / 4), k4 = i % (K / 4);
        int rr = min(rb + r, M - 1);
        ((float4*)(as + r * K))[k4] = ((const float4*)(A + (size_t)rr * K))[k4];
    }
    __syncthreads();

    int warp = tid >> 5, lane = tid & 31;
    int r0 = warp * 8;   // 8 rows per warp
    int c0 = lane * 4;   // 4 contiguous cols per lane

    float acc[8][4];
#pragma unroll
    for (int r = 0; r < 8; r++)
#pragma unroll
        for (int c = 0; c < 4; c++) acc[r][c] = 0.0f;

#pragma unroll 4
    for (int k = 0; k < K; k++) {
        float4 wv = *((const float4*)(ws + k * 128 + c0));
#pragma unroll
        for (int r = 0; r < 8; r++) {
            float a = as[(r0 + r) * K + k];
            acc[r][0] += a * wv.x;
            acc[r][1] += a * wv.y;
            acc[r][2] += a * wv.z;
            acc[r][3] += a * wv.w;
        }
    }

    float4 bv = *((const float4*)(bias + cb + c0));
#pragma unroll
    for (int r = 0; r < 8; r++) {
        int row = rb + r0 + r;
        if (row < M) {
            float4 o;
            o.x = acc[r][0] + bv.x;
            o.y = acc[r][1] + bv.y;
            o.z = acc[r][2] + bv.z;
            o.w = acc[r][3] + bv.w;
            if (RELU) {
                o.x = fmaxf(o.x, 0.0f); o.y = fmaxf(o.y, 0.0f);
                o.z = fmaxf(o.z, 0.0f); o.w = fmaxf(o.w, 0.0f);
            }
            *((float4*)(C + (size_t)row * 256 + cb + c0)) = o;
        }
    }
}

// ---------------- final: z = h4 @ w4[256x2] + b4; log_softmax ---------------
__global__ void final_kernel(const float* __restrict__ h4, const float* __restrict__ w4,
                             const float* __restrict__ b4, float* __restrict__ out, int M) {
    int row = blockIdx.x * (blockDim.x / 32) + (threadIdx.x >> 5);
    if (row >= M) return;
    int lane = threadIdx.x & 31;

    const float4* rp = (const float4*)(h4 + (size_t)row * 256);
    float z0 = 0.0f, z1 = 0.0f;
#pragma unroll
    for (int v = 0; v < 2; v++) {
        float4 a = rp[lane + 32 * v];
        int kb = (lane + 32 * v) * 4;
        float4 w01 = ((const float4*)(w4 + kb * 2))[0];  // {k0c0,k0c1,k1c0,k1c1}
        float4 w23 = ((const float4*)(w4 + kb * 2))[1];  // {k2c0,k2c1,k3c0,k3c1}
        z0 += a.x * w01.x + a.y * w01.z + a.z * w23.x + a.w * w23.z;
        z1 += a.x * w01.y + a.y * w01.w + a.z * w23.y + a.w * w23.w;
    }
#pragma unroll
    for (int o = 16; o; o >>= 1) {
        z0 += __shfl_xor_sync(0xFFFFFFFFu, z0, o);
        z1 += __shfl_xor_sync(0xFFFFFFFFu, z1, o);
    }
    if (lane == 0) {
        z0 += b4[0];
        z1 += b4[1];
        float m = fmaxf(z0, z1);
        float l = m + logf(expf(z0 - m) + expf(z1 - m));
        out[row * 2 + 0] = z0 - l;
        out[row * 2 + 1] = z1 - l;
    }
}

// ---------------- launcher --------------------------------------------------
extern "C" void kernel_launch(void* const* d_in, const int* in_sizes, int n_in,
                              void* d_out, int out_size) {
    const float* x    = (const float*)d_in[0];
    const int*   ei32 = (const int*)d_in[1];   // raw int32 view; dtype detected on-device
    const float* w1 = (const float*)d_in[2]; const float* b1 = (const float*)d_in[3];
    const float* w2 = (const float*)d_in[4]; const float* b2 = (const float*)d_in[5];
    const float* w3 = (const float*)d_in[6]; const float* b3 = (const float*)d_in[7];
    const float* w4 = (const float*)d_in[8]; const float* b4 = (const float*)d_in[9];
    float* out = (float*)d_out;

    // Resolve true device addresses of __device__ scratch once (capture-safe,
    // not stream-ordered, no allocation).
    static int *is64 = nullptr, *deg = nullptr, *off = nullptr;
    static int *cur = nullptr, *csr = nullptr;
    static float *h0, *h1, *h2, *h3, *h4;
    static bool init_done = false;
    const int SMEM128 = (128 * 128 + 64 * 128) * 4;  //  96 KB
    const int SMEM256 = (256 * 128 + 64 * 256) * 4;  // 192 KB
    if (!init_done) {
        cudaGetSymbolAddress((void**)&is64, g_is64);
        cudaGetSymbolAddress((void**)&deg, g_deg);
        cudaGetSymbolAddress((void**)&off, g_off);
        cudaGetSymbolAddress((void**)&cur, g_cur);
        cudaGetSymbolAddress((void**)&csr, g_csr);
        cudaGetSymbolAddress((void**)&h0, g_h0);
        cudaGetSymbolAddress((void**)&h1, g_h1);
        cudaGetSymbolAddress((void**)&h2, g_h2);
        cudaGetSymbolAddress((void**)&h3, g_h3);
        cudaGetSymbolAddress((void**)&h4, g_h4);
        cudaFuncSetAttribute(sgemm_kernel<128, true>,
                             cudaFuncAttributeMaxDynamicSharedMemorySize, SMEM128);
        cudaFuncSetAttribute(sgemm_kernel<256, true>,
                             cudaFuncAttributeMaxDynamicSharedMemorySize, SMEM256);
        init_done = true;
    }

    const int EB = (N_EDGES + 255) / 256;
    const int NB = (N_NODES + 255) / 256;
    const int GB = (N_NODES + 7) / 8;           // warp-per-node kernels
    dim3 gemm_grid((N_NODES + 63) / 64, 2);

    // CSR build (reused by both layers)
    detect_kernel<<<1, 32>>>(ei32, is64);
    zero_deg_kernel<<<NB, 256>>>(deg);
    hist_kernel<<<EB, 256>>>(ei32, is64, deg);
    scan_kernel<<<1, 1024>>>(deg, off, cur);
    fill_kernel<<<EB, 256>>>(ei32, is64, cur, csr);

    // layer 1: h0 = x + agg(x); h1 = relu(h0@w1+b1); h2 = relu(h1@w2+b2)
    gather_kernel<128><<<GB, 256>>>(x, csr, off, h0);
    sgemm_kernel<128, true><<<gemm_grid, 256, SMEM128>>>(h0, w1, b1, h1, N_NODES);
    sgemm_kernel<256, true><<<gemm_grid, 256, SMEM256>>>(h1, w2, b2, h2, N_NODES);

    // layer 2: h3 = h2 + agg(h2); h4 = relu(h3@w3+b3); out = log_softmax(h4@w4+b4)
    gather_kernel<256><<<GB, 256>>>(h2, csr, off, h3);
    sgemm_kernel<256, true><<<gemm_grid, 256, SMEM256>>>(h3, w3, b3, h4, N_NODES);
    final_kernel<<<GB, 256>>>(h4, w4, b4, out, N_NODES);
}

// round 9
// speedup vs baseline: 1.8588x; 1.8588x over previous
#include <cuda_runtime.h>
#include <math.h>
#include <stdint.h>

#define N_NODES 50000
#define N_EDGES 600000
#define D_IN    128
#define D_H     256
#define SCAN_BLKS ((N_NODES + 255) / 256)   // 196

// ---------------- static device scratch (no allocations allowed) ------------
__device__ int   g_is64;
__device__ int   g_deg[N_NODES];
__device__ int   g_off[N_NODES + 1];
__device__ int   g_cur[N_NODES];
__device__ int   g_bsum[SCAN_BLKS];
__device__ int   g_csr[N_EDGES];
__device__ float g_h0[(size_t)N_NODES * D_IN];
__device__ float g_h1[(size_t)N_NODES * D_H];
__device__ float g_h2[(size_t)N_NODES * D_H];
__device__ float g_h3[(size_t)N_NODES * D_H];
__device__ float g_h4[(size_t)N_NODES * D_H];
// tf32 hi/lo split weights (stored as f32 bit patterns of tf32 values)
__device__ float g_w1hi[D_IN * D_H],  g_w1lo[D_IN * D_H];
__device__ float g_w2hi[D_H * D_H],   g_w2lo[D_H * D_H];
__device__ float g_w3hi[D_H * D_H],   g_w3lo[D_H * D_H];

// ---------------- edge dtype detection --------------------------------------
__global__ void detect_kernel(const int* __restrict__ ei32, int* __restrict__ is64) {
    if (threadIdx.x == 0) {
        int all_zero = 1;
        for (int i = 0; i < 128; i++)
            if (ei32[2 * i + 1] != 0) { all_zero = 0; break; }
        *is64 = all_zero;
    }
}
__device__ __forceinline__ int edge_src(const int* ei32, int is64, int i) {
    return is64 ? ei32[2 * i] : ei32[i];
}
__device__ __forceinline__ int edge_dst(const int* ei32, int is64, int i) {
    return is64 ? ei32[2 * N_EDGES + 2 * i] : ei32[N_EDGES + i];
}

// ---------------- CSR build -------------------------------------------------
__global__ void zero_deg_kernel(int* __restrict__ deg) {
    int i = blockIdx.x * blockDim.x + threadIdx.x;
    if (i < N_NODES) deg[i] = 0;
}

__global__ void hist_kernel(const int* __restrict__ ei32, const int* __restrict__ is64p,
                            int* __restrict__ deg) {
    int i = blockIdx.x * blockDim.x + threadIdx.x;
    if (i < N_EDGES) atomicAdd(&deg[edge_dst(ei32, *is64p, i)], 1);
}

// multi-block exclusive scan: phase 1 (per-block scan + block sums)
__global__ void scan1_kernel(const int* __restrict__ deg, int* __restrict__ off,
                             int* __restrict__ bsum) {
    __shared__ int sd[256];
    int tid = threadIdx.x;
    int i = blockIdx.x * 256 + tid;
    int v = (i < N_NODES) ? deg[i] : 0;
    sd[tid] = v;
    __syncthreads();
    for (int d = 1; d < 256; d <<= 1) {
        int t = (tid >= d) ? sd[tid - d] : 0;
        __syncthreads();
        sd[tid] += t;
        __syncthreads();
    }
    if (i < N_NODES) off[i] = sd[tid] - v;  // exclusive within block
    if (tid == 255) bsum[blockIdx.x] = sd[255];
}
// phase 2: scan block sums (SCAN_BLKS <= 256, one block)
__global__ void scan2_kernel(int* __restrict__ bsum) {
    __shared__ int sd[256];
    int tid = threadIdx.x;
    int v = (tid < SCAN_BLKS) ? bsum[tid] : 0;
    sd[tid] = v;
    __syncthreads();
    for (int d = 1; d < 256; d <<= 1) {
        int t = (tid >= d) ? sd[tid - d] : 0;
        __syncthreads();
        sd[tid] += t;
        __syncthreads();
    }
    if (tid < SCAN_BLKS) bsum[tid] = sd[tid] - v;  // exclusive
}
// phase 3: add block offsets, init cursors, set sentinel
__global__ void scan3_kernel(int* __restrict__ off, const int* __restrict__ bsum,
                             int* __restrict__ cur) {
    int i = blockIdx.x * blockDim.x + threadIdx.x;
    if (i < N_NODES) {
        int o = off[i] + bsum[i >> 8];
        off[i] = o;
        cur[i] = o;
    }
    if (i == 0) off[N_NODES] = N_EDGES;
}

__global__ void fill_kernel(const int* __restrict__ ei32, const int* __restrict__ is64p,
                            int* __restrict__ cur, int* __restrict__ csr) {
    int i = blockIdx.x * blockDim.x + threadIdx.x;
    if (i < N_EDGES) {
        int is64 = *is64p;
        int p = atomicAdd(&cur[edge_dst(ei32, is64, i)], 1);
        csr[p] = edge_src(ei32, is64, i);
    }
}

// ---------------- gather aggregation: out[i] = h[i] + sum_{j->i} h[j] -------
template <int D>
__global__ void gather_kernel(const float* __restrict__ h, const int* __restrict__ csr,
                              const int* __restrict__ off, float* __restrict__ out) {
    int node = blockIdx.x * (blockDim.x / 32) + (threadIdx.x >> 5);
    if (node >= N_NODES) return;
    int lane = threadIdx.x & 31;
    constexpr int V = D / 128;

    float4 acc[V];
    const float4* rp = (const float4*)(h + (size_t)node * D);
#pragma unroll
    for (int v = 0; v < V; v++) acc[v] = rp[lane + 32 * v];

    int beg = off[node], end = off[node + 1];
    int e = beg;
    // 4-way unrolled: batch index loads + row loads for MLP
    for (; e + 4 <= end; e += 4) {
        int s0 = csr[e], s1 = csr[e + 1], s2 = csr[e + 2], s3 = csr[e + 3];
        const float4* p0 = (const float4*)(h + (size_t)s0 * D);
        const float4* p1 = (const float4*)(h + (size_t)s1 * D);
        const float4* p2 = (const float4*)(h + (size_t)s2 * D);
        const float4* p3 = (const float4*)(h + (size_t)s3 * D);
#pragma unroll
        for (int v = 0; v < V; v++) {
            float4 t0 = p0[lane + 32 * v];
            float4 t1 = p1[lane + 32 * v];
            float4 t2 = p2[lane + 32 * v];
            float4 t3 = p3[lane + 32 * v];
            acc[v].x += t0.x + t1.x + t2.x + t3.x;
            acc[v].y += t0.y + t1.y + t2.y + t3.y;
            acc[v].z += t0.z + t1.z + t2.z + t3.z;
            acc[v].w += t0.w + t1.w + t2.w + t3.w;
        }
    }
    for (; e < end; e++) {
        int s = csr[e];
        const float4* sp = (const float4*)(h + (size_t)s * D);
#pragma unroll
        for (int v = 0; v < V; v++) {
            float4 t = sp[lane + 32 * v];
            acc[v].x += t.x; acc[v].y += t.y; acc[v].z += t.z; acc[v].w += t.w;
        }
    }
    float4* op = (float4*)(out + (size_t)node * D);
#pragma unroll
    for (int v = 0; v < V; v++) op[lane + 32 * v] = acc[v];
}

// ---------------- weight split: w -> (tf32 hi, tf32 lo) ---------------------
__global__ void wsplit_kernel(const float* __restrict__ w, float* __restrict__ hi,
                              float* __restrict__ lo, int n) {
    int i = blockIdx.x * blockDim.x + threadIdx.x;
    if (i < n) {
        float x = w[i];
        uint32_t h;
        asm("cvt.rna.tf32.f32 %0, %1;" : "=r"(h) : "f"(x));
        float hf = __uint_as_float(h);
        float l = x - hf;
        uint32_t lt;
        asm("cvt.rna.tf32.f32 %0, %1;" : "=r"(lt) : "f"(l));
        hi[i] = hf;
        lo[i] = __uint_as_float(lt);
    }
}

// ---------------- tensor-core GEMM (tf32 split, ~fp32 precision) ------------
// C[M x 256] = relu(A[M x K] @ W[K x 256] + bias)
// Block 128x128, 8 warps (4m x 2n), warp tile 32x64, mma.m16n8k8.tf32.
// Split: a*b ~= ahi*bhi + ahi*blo + alo*bhi  (error ~2^-22)
#define MMA_TF32(c, a, b0, b1)                                                  \
    asm volatile(                                                               \
        "mma.sync.aligned.m16n8k8.row.col.f32.tf32.tf32.f32 "                  \
        "{%0,%1,%2,%3}, {%4,%5,%6,%7}, {%8,%9}, {%0,%1,%2,%3};"                \
        : "+f"(c[0]), "+f"(c[1]), "+f"(c[2]), "+f"(c[3])                        \
        : "r"(a[0]), "r"(a[1]), "r"(a[2]), "r"(a[3]), "r"(b0), "r"(b1))

template <int K>
__global__ void __launch_bounds__(256)
sgemm_tc(const float* __restrict__ A, const float* __restrict__ Whi,
         const float* __restrict__ Wlo, const float* __restrict__ bias,
         float* __restrict__ C, int M) {
    extern __shared__ float sm[];
    float* As = sm;                  // [128][68]  (pad 68: conflict-free frags)
    float* Bh = sm + 128 * 68;       // [64][136]  (pad 136: banks 8*tg+g)
    float* Bl = Bh + 64 * 136;

    const int rb = blockIdx.x * 128;
    const int cb = blockIdx.y * 128;
    int tid = threadIdx.x, wid = tid >> 5, lane = tid & 31;
    int wm = wid & 3, wn = wid >> 2;
    int g = lane >> 2, tg = lane & 3;

    float acc[2][8][4];
#pragma unroll
    for (int mt = 0; mt < 2; mt++)
#pragma unroll
        for (int nt = 0; nt < 8; nt++)
#pragma unroll
            for (int q = 0; q < 4; q++) acc[mt][nt][q] = 0.0f;

    for (int kc = 0; kc < K; kc += 64) {
        __syncthreads();
        // A chunk: 128 rows x 64 cols (8 float4/thread), row-clamped
        for (int t = tid; t < 128 * 16; t += 256) {
            int r = t >> 4, c4 = t & 15;
            int rr = min(rb + r, M - 1);
            float4 v = ((const float4*)(A + (size_t)rr * K + kc))[c4];
            *(float4*)(As + r * 68 + c4 * 4) = v;
        }
        // W hi/lo chunk: 64 rows x 128 cols
        for (int t = tid; t < 64 * 32; t += 256) {
            int r = t >> 5, c4 = t & 31;
            float4 vh = ((const float4*)(Whi + (size_t)(kc + r) * 256 + cb))[c4];
            float4 vl = ((const float4*)(Wlo + (size_t)(kc + r) * 256 + cb))[c4];
            *(float4*)(Bh + r * 136 + c4 * 4) = vh;
            *(float4*)(Bl + r * 136 + c4 * 4) = vl;
        }
        __syncthreads();

#pragma unroll
        for (int k8 = 0; k8 < 8; k8++) {
            uint32_t ah[2][4], al[2][4];
#pragma unroll
            for (int mt = 0; mt < 2; mt++) {
                int r0 = wm * 32 + mt * 16 + g;
#pragma unroll
                for (int q = 0; q < 4; q++) {
                    int rr = r0 + (q & 1) * 8;
                    int cc = k8 * 8 + tg + (q >> 1) * 4;
                    float a = As[rr * 68 + cc];
                    uint32_t h;
                    asm("cvt.rna.tf32.f32 %0, %1;" : "=r"(h) : "f"(a));
                    float l = a - __uint_as_float(h);
                    uint32_t lt;
                    asm("cvt.rna.tf32.f32 %0, %1;" : "=r"(lt) : "f"(l));
                    ah[mt][q] = h;
                    al[mt][q] = lt;
                }
            }
#pragma unroll
            for (int nt = 0; nt < 8; nt++) {
                int col = wn * 64 + nt * 8 + g;
                int kr = k8 * 8 + tg;
                uint32_t bh0 = __float_as_uint(Bh[kr * 136 + col]);
                uint32_t bh1 = __float_as_uint(Bh[(kr + 4) * 136 + col]);
                uint32_t bl0 = __float_as_uint(Bl[kr * 136 + col]);
                uint32_t bl1 = __float_as_uint(Bl[(kr + 4) * 136 + col]);
#pragma unroll
                for (int mt = 0; mt < 2; mt++) {
                    MMA_TF32(acc[mt][nt], ah[mt], bh0, bh1);
                    MMA_TF32(acc[mt][nt], ah[mt], bl0, bl1);
                    MMA_TF32(acc[mt][nt], al[mt], bh0, bh1);
                }
            }
        }
    }

    // epilogue: bias + relu, float2 stores
#pragma unroll
    for (int mt = 0; mt < 2; mt++) {
        int row0 = rb + wm * 32 + mt * 16 + g;
#pragma unroll
        for (int nt = 0; nt < 8; nt++) {
            int col = cb + wn * 64 + nt * 8 + 2 * tg;
            float b0 = bias[col], b1 = bias[col + 1];
            if (row0 < M) {
                float2 o;
                o.x = fmaxf(acc[mt][nt][0] + b0, 0.0f);
                o.y = fmaxf(acc[mt][nt][1] + b1, 0.0f);
                *(float2*)(C + (size_t)row0 * 256 + col) = o;
            }
            if (row0 + 8 < M) {
                float2 o;
                o.x = fmaxf(acc[mt][nt][2] + b0, 0.0f);
                o.y = fmaxf(acc[mt][nt][3] + b1, 0.0f);
                *(float2*)(C + (size_t)(row0 + 8) * 256 + col) = o;
            }
        }
    }
}

// ---------------- final: z = h4 @ w4[256x2] + b4; log_softmax ---------------
__global__ void final_kernel(const float* __restrict__ h4, const float* __restrict__ w4,
                             const float* __restrict__ b4, float* __restrict__ out, int M) {
    int row = blockIdx.x * (blockDim.x / 32) + (threadIdx.x >> 5);
    if (row >= M) return;
    int lane = threadIdx.x & 31;

    const float4* rp = (const float4*)(h4 + (size_t)row * 256);
    float z0 = 0.0f, z1 = 0.0f;
#pragma unroll
    for (int v = 0; v < 2; v++) {
        float4 a = rp[lane + 32 * v];
        int kb = (lane + 32 * v) * 4;
        float4 w01 = ((const float4*)(w4 + kb * 2))[0];
        float4 w23 = ((const float4*)(w4 + kb * 2))[1];
        z0 += a.x * w01.x + a.y * w01.z + a.z * w23.x + a.w * w23.z;
        z1 += a.x * w01.y + a.y * w01.w + a.z * w23.y + a.w * w23.w;
    }
#pragma unroll
    for (int o = 16; o; o >>= 1) {
        z0 += __shfl_xor_sync(0xFFFFFFFFu, z0, o);
        z1 += __shfl_xor_sync(0xFFFFFFFFu, z1, o);
    }
    if (lane == 0) {
        z0 += b4[0];
        z1 += b4[1];
        float m = fmaxf(z0, z1);
        float l = m + logf(expf(z0 - m) + expf(z1 - m));
        out[row * 2 + 0] = z0 - l;
        out[row * 2 + 1] = z1 - l;
    }
}

// ---------------- launcher --------------------------------------------------
extern "C" void kernel_launch(void* const* d_in, const int* in_sizes, int n_in,
                              void* d_out, int out_size) {
    const float* x    = (const float*)d_in[0];
    const int*   ei32 = (const int*)d_in[1];
    const float* w1 = (const float*)d_in[2]; const float* b1 = (const float*)d_in[3];
    const float* w2 = (const float*)d_in[4]; const float* b2 = (const float*)d_in[5];
    const float* w3 = (const float*)d_in[6]; const float* b3 = (const float*)d_in[7];
    const float* w4 = (const float*)d_in[8]; const float* b4 = (const float*)d_in[9];
    float* out = (float*)d_out;

    static int *is64, *deg, *off, *cur, *csr, *bsum;
    static float *h0, *h1, *h2, *h3, *h4;
    static float *w1hi, *w1lo, *w2hi, *w2lo, *w3hi, *w3lo;
    static bool init_done = false;
    const int SMEM_TC = (128 * 68 + 2 * 64 * 136) * 4;  // 104448 B
    if (!init_done) {
        cudaGetSymbolAddress((void**)&is64, g_is64);
        cudaGetSymbolAddress((void**)&deg, g_deg);
        cudaGetSymbolAddress((void**)&off, g_off);
        cudaGetSymbolAddress((void**)&cur, g_cur);
        cudaGetSymbolAddress((void**)&csr, g_csr);
        cudaGetSymbolAddress((void**)&bsum, g_bsum);
        cudaGetSymbolAddress((void**)&h0, g_h0);
        cudaGetSymbolAddress((void**)&h1, g_h1);
        cudaGetSymbolAddress((void**)&h2, g_h2);
        cudaGetSymbolAddress((void**)&h3, g_h3);
        cudaGetSymbolAddress((void**)&h4, g_h4);
        cudaGetSymbolAddress((void**)&w1hi, g_w1hi);
        cudaGetSymbolAddress((void**)&w1lo, g_w1lo);
        cudaGetSymbolAddress((void**)&w2hi, g_w2hi);
        cudaGetSymbolAddress((void**)&w2lo, g_w2lo);
        cudaGetSymbolAddress((void**)&w3hi, g_w3hi);
        cudaGetSymbolAddress((void**)&w3lo, g_w3lo);
        cudaFuncSetAttribute(sgemm_tc<128>,
                             cudaFuncAttributeMaxDynamicSharedMemorySize, SMEM_TC);
        cudaFuncSetAttribute(sgemm_tc<256>,
                             cudaFuncAttributeMaxDynamicSharedMemorySize, SMEM_TC);
        init_done = true;
    }

    const int EB = (N_EDGES + 255) / 256;
    const int NB = (N_NODES + 255) / 256;
    const int GB = (N_NODES + 7) / 8;
    dim3 tc_grid((N_NODES + 127) / 128, 2);

    // weight split (tiny; every call for determinism)
    wsplit_kernel<<<(D_IN * D_H + 255) / 256, 256>>>(w1, w1hi, w1lo, D_IN * D_H);
    wsplit_kernel<<<(D_H * D_H + 255) / 256, 256>>>(w2, w2hi, w2lo, D_H * D_H);
    wsplit_kernel<<<(D_H * D_H + 255) / 256, 256>>>(w3, w3hi, w3lo, D_H * D_H);

    // CSR build
    detect_kernel<<<1, 32>>>(ei32, is64);
    zero_deg_kernel<<<NB, 256>>>(deg);
    hist_kernel<<<EB, 256>>>(ei32, is64, deg);
    scan1_kernel<<<SCAN_BLKS, 256>>>(deg, off, bsum);
    scan2_kernel<<<1, 256>>>(bsum);
    scan3_kernel<<<NB, 256>>>(off, bsum, cur);
    fill_kernel<<<EB, 256>>>(ei32, is64, cur, csr);

    // layer 1
    gather_kernel<128><<<GB, 256>>>(x, csr, off, h0);
    sgemm_tc<128><<<tc_grid, 256, SMEM_TC>>>(h0, w1hi, w1lo, b1, h1, N_NODES);
    sgemm_tc<256><<<tc_grid, 256, SMEM_TC>>>(h1, w2hi, w2lo, b2, h2, N_NODES);

    // layer 2
    gather_kernel<256><<<GB, 256>>>(h2, csr, off, h3);
    sgemm_tc<256><<<tc_grid, 256, SMEM_TC>>>(h3, w3hi, w3lo, b3, h4, N_NODES);
    final_kernel<<<GB, 256>>>(h4, w4, b4, out, N_NODES);
}

// round 14
// speedup vs baseline: 2.5970x; 1.3971x over previous
#include <cuda_runtime.h>
#include <cuda_bf16.h>
#include <math.h>
#include <stdint.h>

#define N_NODES 50000
#define N_EDGES 600000
#define D_IN    128
#define D_H     256
#define SCAN_BLKS ((N_NODES + 255) / 256)   // 196

// ---------------- static device scratch (no allocations allowed) ------------
__device__ int   g_is64;
__device__ int   g_deg[N_NODES];
__device__ int   g_off[N_NODES + 1];
__device__ int   g_cur[N_NODES];
__device__ int   g_bsum[SCAN_BLKS];
__device__ int   g_csr[N_EDGES];
__device__ float g_h0[(size_t)N_NODES * D_IN];
__device__ float g_h1[(size_t)N_NODES * D_H];
__device__ float g_h2[(size_t)N_NODES * D_H];
__device__ float g_h3[(size_t)N_NODES * D_H];
__device__ float g_h4[(size_t)N_NODES * D_H];
// transposed bf16 hi/lo split weights: Wt[n][k] = W[k][n]
__device__ __align__(16) __nv_bfloat16 g_w1hi[D_H * D_IN], g_w1lo[D_H * D_IN];
__device__ __align__(16) __nv_bfloat16 g_w2hi[D_H * D_H],  g_w2lo[D_H * D_H];
__device__ __align__(16) __nv_bfloat16 g_w3hi[D_H * D_H],  g_w3lo[D_H * D_H];

// ---------------- edge dtype detection --------------------------------------
__global__ void detect_kernel(const int* __restrict__ ei32, int* __restrict__ is64) {
    if (threadIdx.x == 0) {
        int all_zero = 1;
        for (int i = 0; i < 128; i++)
            if (ei32[2 * i + 1] != 0) { all_zero = 0; break; }
        *is64 = all_zero;
    }
}
__device__ __forceinline__ int edge_src(const int* ei32, int is64, int i) {
    return is64 ? ei32[2 * i] : ei32[i];
}
__device__ __forceinline__ int edge_dst(const int* ei32, int is64, int i) {
    return is64 ? ei32[2 * N_EDGES + 2 * i] : ei32[N_EDGES + i];
}

// ---------------- CSR build -------------------------------------------------
__global__ void zero_deg_kernel(int* __restrict__ deg) {
    int i = blockIdx.x * blockDim.x + threadIdx.x;
    if (i < N_NODES) deg[i] = 0;
}
__global__ void hist_kernel(const int* __restrict__ ei32, const int* __restrict__ is64p,
                            int* __restrict__ deg) {
    int i = blockIdx.x * blockDim.x + threadIdx.x;
    if (i < N_EDGES) atomicAdd(&deg[edge_dst(ei32, *is64p, i)], 1);
}
__global__ void scan1_kernel(const int* __restrict__ deg, int* __restrict__ off,
                             int* __restrict__ bsum) {
    __shared__ int sd[256];
    int tid = threadIdx.x;
    int i = blockIdx.x * 256 + tid;
    int v = (i < N_NODES) ? deg[i] : 0;
    sd[tid] = v;
    __syncthreads();
    for (int d = 1; d < 256; d <<= 1) {
        int t = (tid >= d) ? sd[tid - d] : 0;
        __syncthreads();
        sd[tid] += t;
        __syncthreads();
    }
    if (i < N_NODES) off[i] = sd[tid] - v;
    if (tid == 255) bsum[blockIdx.x] = sd[255];
}
__global__ void scan2_kernel(int* __restrict__ bsum) {
    __shared__ int sd[256];
    int tid = threadIdx.x;
    int v = (tid < SCAN_BLKS) ? bsum[tid] : 0;
    sd[tid] = v;
    __syncthreads();
    for (int d = 1; d < 256; d <<= 1) {
        int t = (tid >= d) ? sd[tid - d] : 0;
        __syncthreads();
        sd[tid] += t;
        __syncthreads();
    }
    if (tid < SCAN_BLKS) bsum[tid] = sd[tid] - v;
}
__global__ void scan3_kernel(int* __restrict__ off, const int* __restrict__ bsum,
                             int* __restrict__ cur) {
    int i = blockIdx.x * blockDim.x + threadIdx.x;
    if (i < N_NODES) {
        int o = off[i] + bsum[i >> 8];
        off[i] = o;
        cur[i] = o;
    }
    if (i == 0) off[N_NODES] = N_EDGES;
}
__global__ void fill_kernel(const int* __restrict__ ei32, const int* __restrict__ is64p,
                            int* __restrict__ cur, int* __restrict__ csr) {
    int i = blockIdx.x * blockDim.x + threadIdx.x;
    if (i < N_EDGES) {
        int is64 = *is64p;
        int p = atomicAdd(&cur[edge_dst(ei32, is64, i)], 1);
        csr[p] = edge_src(ei32, is64, i);
    }
}

// ---------------- gather aggregation: out[i] = h[i] + sum_{j->i} h[j] -------
template <int D>
__global__ void gather_kernel(const float* __restrict__ h, const int* __restrict__ csr,
                              const int* __restrict__ off, float* __restrict__ out) {
    int node = blockIdx.x * (blockDim.x / 32) + (threadIdx.x >> 5);
    if (node >= N_NODES) return;
    int lane = threadIdx.x & 31;
    constexpr int V = D / 128;

    float4 acc[V];
    const float4* rp = (const float4*)(h + (size_t)node * D);
#pragma unroll
    for (int v = 0; v < V; v++) acc[v] = rp[lane + 32 * v];

    int beg = off[node], end = off[node + 1];
    int e = beg;
    for (; e + 4 <= end; e += 4) {
        int s0 = csr[e], s1 = csr[e + 1], s2 = csr[e + 2], s3 = csr[e + 3];
        const float4* p0 = (const float4*)(h + (size_t)s0 * D);
        const float4* p1 = (const float4*)(h + (size_t)s1 * D);
        const float4* p2 = (const float4*)(h + (size_t)s2 * D);
        const float4* p3 = (const float4*)(h + (size_t)s3 * D);
#pragma unroll
        for (int v = 0; v < V; v++) {
            float4 t0 = p0[lane + 32 * v];
            float4 t1 = p1[lane + 32 * v];
            float4 t2 = p2[lane + 32 * v];
            float4 t3 = p3[lane + 32 * v];
            acc[v].x += t0.x + t1.x + t2.x + t3.x;
            acc[v].y += t0.y + t1.y + t2.y + t3.y;
            acc[v].z += t0.z + t1.z + t2.z + t3.z;
            acc[v].w += t0.w + t1.w + t2.w + t3.w;
        }
    }
    for (; e < end; e++) {
        int s = csr[e];
        const float4* sp = (const float4*)(h + (size_t)s * D);
#pragma unroll
        for (int v = 0; v < V; v++) {
            float4 t = sp[lane + 32 * v];
            acc[v].x += t.x; acc[v].y += t.y; acc[v].z += t.z; acc[v].w += t.w;
        }
    }
    float4* op = (float4*)(out + (size_t)node * D);
#pragma unroll
    for (int v = 0; v < V; v++) op[lane + 32 * v] = acc[v];
}

// ---------------- weight transpose + bf16 hi/lo split ------------------------
// W[k][256] -> Wt_hi[n][K], Wt_lo[n][K]  (bf16)
__global__ void wsplit_t_kernel(const float* __restrict__ w, __nv_bfloat16* __restrict__ hi,
                                __nv_bfloat16* __restrict__ lo, int K) {
    int i = blockIdx.x * blockDim.x + threadIdx.x;
    if (i < K * 256) {
        int k = i >> 8, n = i & 255;
        float x = w[i];
        __nv_bfloat16 h = __float2bfloat16(x);
        float r = x - __bfloat162float(h);
        hi[(size_t)n * K + k] = h;
        lo[(size_t)n * K + k] = __float2bfloat16(r);
    }
}

// ---------------- bf16-split tensor-core GEMM (~fp32 precision) -------------
// C[M x 256] = relu(A[M x K] @ W[K x 256] + bias)
// Block 128x128, 8 warps (4m x 2n), warp tile 32x64, mma.m16n8k16.bf16.
// a*b ~= ahi*bhi + ahi*blo + alo*bhi  (dropped lo*lo <= 2^-16 rel)
// SMEM tiles: rows padded to 36 words (72 bf16): frag bank = (4g+tg) -> conflict-free.
#define MMA_BF16(c, a, b0, b1)                                                  \
    asm volatile(                                                               \
        "mma.sync.aligned.m16n8k16.row.col.f32.bf16.bf16.f32 "                 \
        "{%0,%1,%2,%3}, {%4,%5,%6,%7}, {%8,%9}, {%0,%1,%2,%3};"                \
        : "+f"(c[0]), "+f"(c[1]), "+f"(c[2]), "+f"(c[3])                        \
        : "r"(a[0]), "r"(a[1]), "r"(a[2]), "r"(a[3]), "r"(b0), "r"(b1))

#define TROW 36   // padded row stride in 32-bit words (= 72 bf16)

template <int K>
__global__ void __launch_bounds__(256)
sgemm_bf16(const float* __restrict__ A, const __nv_bfloat16* __restrict__ Whi,
           const __nv_bfloat16* __restrict__ Wlo, const float* __restrict__ bias,
           float* __restrict__ C, int M) {
    extern __shared__ uint32_t smw[];
    uint32_t* Ah = smw;                 // [128][TROW]
    uint32_t* Al = Ah + 128 * TROW;
    uint32_t* Bh = Al + 128 * TROW;
    uint32_t* Bl = Bh + 128 * TROW;

    const int rb = blockIdx.x * 128;
    const int cb = blockIdx.y * 128;
    int tid = threadIdx.x, wid = tid >> 5, lane = tid & 31;
    int wm = wid & 3, wn = wid >> 2;
    int g = lane >> 2, tg = lane & 3;

    float acc[2][8][4];
#pragma unroll
    for (int mt = 0; mt < 2; mt++)
#pragma unroll
        for (int nt = 0; nt < 8; nt++)
#pragma unroll
            for (int q = 0; q < 4; q++) acc[mt][nt][q] = 0.0f;

    for (int kc = 0; kc < K; kc += 64) {
        __syncthreads();
        // A chunk: 128 rows x 64 f32 -> bf16 hi/lo (split once here)
#pragma unroll
        for (int it = 0; it < 8; it++) {
            int idx = it * 256 + tid;          // 0..2047
            int r = idx >> 4, gp = idx & 15;   // 16 float4 per row
            int rr = min(rb + r, M - 1);
            float4 v = ((const float4*)(A + (size_t)rr * K + kc))[gp];
            float f[4] = {v.x, v.y, v.z, v.w};
            __nv_bfloat16 hi4[4], lo4[4];
#pragma unroll
            for (int q = 0; q < 4; q++) {
                hi4[q] = __float2bfloat16(f[q]);
                lo4[q] = __float2bfloat16(f[q] - __bfloat162float(hi4[q]));
            }
            *(uint2*)(Ah + r * TROW + gp * 2) = *(uint2*)hi4;
            *(uint2*)(Al + r * TROW + gp * 2) = *(uint2*)lo4;
        }
        // B chunk: 128 n-rows x 64 k bf16 (pre-transposed/split in global)
#pragma unroll
        for (int it = 0; it < 4; it++) {
            int idx = it * 256 + tid;          // 0..1023
            int n = idx >> 3, gp = idx & 7;    // 8 x uint4 per row
            uint4 vh = *(const uint4*)(Whi + (size_t)(cb + n) * K + kc + gp * 8);
            uint4 vl = *(const uint4*)(Wlo + (size_t)(cb + n) * K + kc + gp * 8);
            *(uint4*)(Bh + n * TROW + gp * 4) = vh;
            *(uint4*)(Bl + n * TROW + gp * 4) = vl;
        }
        __syncthreads();

#pragma unroll
        for (int s = 0; s < 4; s++) {          // 4 x k16 per 64-chunk
            uint32_t ah[2][4], al[2][4];
#pragma unroll
            for (int mt = 0; mt < 2; mt++) {
                int base = (wm * 32 + mt * 16 + g) * TROW + s * 8 + tg;
                ah[mt][0] = Ah[base];
                ah[mt][1] = Ah[base + 8 * TROW];
                ah[mt][2] = Ah[base + 4];
                ah[mt][3] = Ah[base + 8 * TROW + 4];
                al[mt][0] = Al[base];
                al[mt][1] = Al[base + 8 * TROW];
                al[mt][2] = Al[base + 4];
                al[mt][3] = Al[base + 8 * TROW + 4];
            }
#pragma unroll
            for (int nt = 0; nt < 8; nt++) {
                int wb = (wn * 64 + nt * 8 + g) * TROW + s * 8 + tg;
                uint32_t bh0 = Bh[wb], bh1 = Bh[wb + 4];
                uint32_t bl0 = Bl[wb], bl1 = Bl[wb + 4];
#pragma unroll
                for (int mt = 0; mt < 2; mt++) {
                    MMA_BF16(acc[mt][nt], ah[mt], bh0, bh1);
                    MMA_BF16(acc[mt][nt], ah[mt], bl0, bl1);
                    MMA_BF16(acc[mt][nt], al[mt], bh0, bh1);
                }
            }
        }
    }

    // epilogue: bias + relu, float2 stores
#pragma unroll
    for (int mt = 0; mt < 2; mt++) {
        int row0 = rb + wm * 32 + mt * 16 + g;
#pragma unroll
        for (int nt = 0; nt < 8; nt++) {
            int col = cb + wn * 64 + nt * 8 + 2 * tg;
            float b0 = bias[col], b1 = bias[col + 1];
            if (row0 < M) {
                float2 o;
                o.x = fmaxf(acc[mt][nt][0] + b0, 0.0f);
                o.y = fmaxf(acc[mt][nt][1] + b1, 0.0f);
                *(float2*)(C + (size_t)row0 * 256 + col) = o;
            }
            if (row0 + 8 < M) {
                float2 o;
                o.x = fmaxf(acc[mt][nt][2] + b0, 0.0f);
                o.y = fmaxf(acc[mt][nt][3] + b1, 0.0f);
                *(float2*)(C + (size_t)(row0 + 8) * 256 + col) = o;
            }
        }
    }
}

// ---------------- final: z = h4 @ w4[256x2] + b4; log_softmax ---------------
__global__ void final_kernel(const float* __restrict__ h4, const float* __restrict__ w4,
                             const float* __restrict__ b4, float* __restrict__ out, int M) {
    int row = blockIdx.x * (blockDim.x / 32) + (threadIdx.x >> 5);
    if (row >= M) return;
    int lane = threadIdx.x & 31;

    const float4* rp = (const float4*)(h4 + (size_t)row * 256);
    float z0 = 0.0f, z1 = 0.0f;
#pragma unroll
    for (int v = 0; v < 2; v++) {
        float4 a = rp[lane + 32 * v];
        int kb = (lane + 32 * v) * 4;
        float4 w01 = ((const float4*)(w4 + kb * 2))[0];
        float4 w23 = ((const float4*)(w4 + kb * 2))[1];
        z0 += a.x * w01.x + a.y * w01.z + a.z * w23.x + a.w * w23.z;
        z1 += a.x * w01.y + a.y * w01.w + a.z * w23.y + a.w * w23.w;
    }
#pragma unroll
    for (int o = 16; o; o >>= 1) {
        z0 += __shfl_xor_sync(0xFFFFFFFFu, z0, o);
        z1 += __shfl_xor_sync(0xFFFFFFFFu, z1, o);
    }
    if (lane == 0) {
        z0 += b4[0];
        z1 += b4[1];
        float m = fmaxf(z0, z1);
        float l = m + logf(expf(z0 - m) + expf(z1 - m));
        out[row * 2 + 0] = z0 - l;
        out[row * 2 + 1] = z1 - l;
    }
}

// ---------------- launcher --------------------------------------------------
extern "C" void kernel_launch(void* const* d_in, const int* in_sizes, int n_in,
                              void* d_out, int out_size) {
    const float* x    = (const float*)d_in[0];
    const int*   ei32 = (const int*)d_in[1];
    const float* w1 = (const float*)d_in[2]; const float* b1 = (const float*)d_in[3];
    const float* w2 = (const float*)d_in[4]; const float* b2 = (const float*)d_in[5];
    const float* w3 = (const float*)d_in[6]; const float* b3 = (const float*)d_in[7];
    const float* w4 = (const float*)d_in[8]; const float* b4 = (const float*)d_in[9];
    float* out = (float*)d_out;

    static int *is64, *deg, *off, *cur, *csr, *bsum;
    static float *h0, *h1, *h2, *h3, *h4;
    static __nv_bfloat16 *w1hi, *w1lo, *w2hi, *w2lo, *w3hi, *w3lo;
    static bool init_done = false;
    const int SMEM_BF = 4 * 128 * TROW * 4;   // 73728 B
    if (!init_done) {
        cudaGetSymbolAddress((void**)&is64, g_is64);
        cudaGetSymbolAddress((void**)&deg, g_deg);
        cudaGetSymbolAddress((void**)&off, g_off);
        cudaGetSymbolAddress((void**)&cur, g_cur);
        cudaGetSymbolAddress((void**)&csr, g_csr);
        cudaGetSymbolAddress((void**)&bsum, g_bsum);
        cudaGetSymbolAddress((void**)&h0, g_h0);
        cudaGetSymbolAddress((void**)&h1, g_h1);
        cudaGetSymbolAddress((void**)&h2, g_h2);
        cudaGetSymbolAddress((void**)&h3, g_h3);
        cudaGetSymbolAddress((void**)&h4, g_h4);
        cudaGetSymbolAddress((void**)&w1hi, g_w1hi);
        cudaGetSymbolAddress((void**)&w1lo, g_w1lo);
        cudaGetSymbolAddress((void**)&w2hi, g_w2hi);
        cudaGetSymbolAddress((void**)&w2lo, g_w2lo);
        cudaGetSymbolAddress((void**)&w3hi, g_w3hi);
        cudaGetSymbolAddress((void**)&w3lo, g_w3lo);
        cudaFuncSetAttribute(sgemm_bf16<128>,
                             cudaFuncAttributeMaxDynamicSharedMemorySize, SMEM_BF);
        cudaFuncSetAttribute(sgemm_bf16<256>,
                             cudaFuncAttributeMaxDynamicSharedMemorySize, SMEM_BF);
        init_done = true;
    }

    const int EB = (N_EDGES + 255) / 256;
    const int NB = (N_NODES + 255) / 256;
    const int GB = (N_NODES + 7) / 8;
    dim3 bf_grid((N_NODES + 127) / 128, 2);

    // weight transpose + bf16 split (tiny; every call for determinism)
    wsplit_t_kernel<<<(D_IN * D_H + 255) / 256, 256>>>(w1, w1hi, w1lo, D_IN);
    wsplit_t_kernel<<<(D_H * D_H + 255) / 256, 256>>>(w2, w2hi, w2lo, D_H);
    wsplit_t_kernel<<<(D_H * D_H + 255) / 256, 256>>>(w3, w3hi, w3lo, D_H);

    // CSR build
    detect_kernel<<<1, 32>>>(ei32, is64);
    zero_deg_kernel<<<NB, 256>>>(deg);
    hist_kernel<<<EB, 256>>>(ei32, is64, deg);
    scan1_kernel<<<SCAN_BLKS, 256>>>(deg, off, bsum);
    scan2_kernel<<<1, 256>>>(bsum);
    scan3_kernel<<<NB, 256>>>(off, bsum, cur);
    fill_kernel<<<EB, 256>>>(ei32, is64, cur, csr);

    // layer 1
    gather_kernel<128><<<GB, 256>>>(x, csr, off, h0);
    sgemm_bf16<128><<<bf_grid, 256, SMEM_BF>>>(h0, w1hi, w1lo, b1, h1, N_NODES);
    sgemm_bf16<256><<<bf_grid, 256, SMEM_BF>>>(h1, w2hi, w2lo, b2, h2, N_NODES);

    // layer 2
    gather_kernel<256><<<GB, 256>>>(h2, csr, off, h3);
    sgemm_bf16<256><<<bf_grid, 256, SMEM_BF>>>(h3, w3hi, w3lo, b3, h4, N_NODES);
    final_kernel<<<GB, 256>>>(h4, w4, b4, out, N_NODES);
}

// round 15
// speedup vs baseline: 2.8280x; 1.0890x over previous
#include <cuda_runtime.h>
#include <cuda_bf16.h>
#include <math.h>
#include <stdint.h>

#define N_NODES 50000
#define N_EDGES 600000
#define D_IN    128
#define D_H     256
#define SCAN_BLKS ((N_NODES + 255) / 256)   // 196

// ---------------- static device scratch (no allocations allowed) ------------
__device__ int   g_deg[N_NODES];
__device__ int   g_off[N_NODES + 1];
__device__ int   g_cur[N_NODES];
__device__ int   g_bsum[SCAN_BLKS];
__device__ int   g_csr[N_EDGES];
__device__ float g_h0[(size_t)N_NODES * D_IN];
__device__ float g_h1[(size_t)N_NODES * D_H];
__device__ float g_h2[(size_t)N_NODES * D_H];
__device__ float g_h3[(size_t)N_NODES * D_H];
// transposed bf16 hi/lo split weights: Wt[n][k] = W[k][n]
__device__ __align__(16) __nv_bfloat16 g_w1hi[D_H * D_IN], g_w1lo[D_H * D_IN];
__device__ __align__(16) __nv_bfloat16 g_w2hi[D_H * D_H],  g_w2lo[D_H * D_H];
__device__ __align__(16) __nv_bfloat16 g_w3hi[D_H * D_H],  g_w3lo[D_H * D_H];

// ---------------- per-block edge dtype detection -----------------------------
// Node ids < 50000: if buffer is little-endian int64, odd 32-bit words are 0.
// For int32 data each odd word is a random id (=0 w.p. 2e-5); 8 in a row ~ 0.
__device__ __forceinline__ int block_detect_is64(const int* __restrict__ ei32) {
    __shared__ int s_is64;
    if (threadIdx.x == 0) {
        int az = 1;
#pragma unroll
        for (int i = 0; i < 8; i++)
            if (ei32[2 * i + 1] != 0) { az = 0; break; }
        s_is64 = az;
    }
    __syncthreads();
    return s_is64;
}
__device__ __forceinline__ int edge_src(const int* ei32, int is64, int i) {
    return is64 ? ei32[2 * i] : ei32[i];
}
__device__ __forceinline__ int edge_dst(const int* ei32, int is64, int i) {
    return is64 ? ei32[2 * N_EDGES + 2 * i] : ei32[N_EDGES + i];
}

// ---------------- prep: zero degrees + transpose/split all weights ----------
// i < 50000: deg=0.  Weight split ranges: [0,32768) w1, [32768,98304) w2,
// [98304,163840) w3.  Wt[n][k] = bf16hi/lo of W[k][n].
__global__ void prep_kernel(const float* __restrict__ w1, const float* __restrict__ w2,
                            const float* __restrict__ w3,
                            __nv_bfloat16* __restrict__ w1hi, __nv_bfloat16* __restrict__ w1lo,
                            __nv_bfloat16* __restrict__ w2hi, __nv_bfloat16* __restrict__ w2lo,
                            __nv_bfloat16* __restrict__ w3hi, __nv_bfloat16* __restrict__ w3lo,
                            int* __restrict__ deg) {
    int i = blockIdx.x * blockDim.x + threadIdx.x;
    if (i < N_NODES) deg[i] = 0;

    const float* w; __nv_bfloat16 *hi, *lo; int j, K;
    if (i < 32768)       { w = w1; hi = w1hi; lo = w1lo; j = i;          K = D_IN; }
    else if (i < 98304)  { w = w2; hi = w2hi; lo = w2lo; j = i - 32768;  K = D_H; }
    else if (i < 163840) { w = w3; hi = w3hi; lo = w3lo; j = i - 98304;  K = D_H; }
    else return;
    int k = j >> 8, n = j & 255;
    float x = w[j];
    __nv_bfloat16 h = __float2bfloat16(x);
    float r = x - __bfloat162float(h);
    hi[(size_t)n * K + k] = h;
    lo[(size_t)n * K + k] = __float2bfloat16(r);
}

// ---------------- CSR build -------------------------------------------------
__global__ void hist_kernel(const int* __restrict__ ei32, int* __restrict__ deg) {
    int is64 = block_detect_is64(ei32);
    int i = blockIdx.x * blockDim.x + threadIdx.x;
    if (i < N_EDGES) atomicAdd(&deg[edge_dst(ei32, is64, i)], 1);
}
__global__ void scan1_kernel(const int* __restrict__ deg, int* __restrict__ off,
                             int* __restrict__ bsum) {
    __shared__ int sd[256];
    int tid = threadIdx.x;
    int i = blockIdx.x * 256 + tid;
    int v = (i < N_NODES) ? deg[i] : 0;
    sd[tid] = v;
    __syncthreads();
    for (int d = 1; d < 256; d <<= 1) {
        int t = (tid >= d) ? sd[tid - d] : 0;
        __syncthreads();
        sd[tid] += t;
        __syncthreads();
    }
    if (i < N_NODES) off[i] = sd[tid] - v;
    if (tid == 255) bsum[blockIdx.x] = sd[255];
}
__global__ void scan2_kernel(int* __restrict__ bsum) {
    __shared__ int sd[256];
    int tid = threadIdx.x;
    int v = (tid < SCAN_BLKS) ? bsum[tid] : 0;
    sd[tid] = v;
    __syncthreads();
    for (int d = 1; d < 256; d <<= 1) {
        int t = (tid >= d) ? sd[tid - d] : 0;
        __syncthreads();
        sd[tid] += t;
        __syncthreads();
    }
    if (tid < SCAN_BLKS) bsum[tid] = sd[tid] - v;
}
__global__ void scan3_kernel(int* __restrict__ off, const int* __restrict__ bsum,
                             int* __restrict__ cur) {
    int i = blockIdx.x * blockDim.x + threadIdx.x;
    if (i < N_NODES) {
        int o = off[i] + bsum[i >> 8];
        off[i] = o;
        cur[i] = o;
    }
    if (i == 0) off[N_NODES] = N_EDGES;
}
__global__ void fill_kernel(const int* __restrict__ ei32,
                            int* __restrict__ cur, int* __restrict__ csr) {
    int is64 = block_detect_is64(ei32);
    int i = blockIdx.x * blockDim.x + threadIdx.x;
    if (i < N_EDGES) {
        int p = atomicAdd(&cur[edge_dst(ei32, is64, i)], 1);
        csr[p] = edge_src(ei32, is64, i);
    }
}

// ---------------- gather aggregation: out[i] = h[i] + sum_{j->i} h[j] -------
template <int D>
__global__ void gather_kernel(const float* __restrict__ h, const int* __restrict__ csr,
                              const int* __restrict__ off, float* __restrict__ out) {
    int node = blockIdx.x * (blockDim.x / 32) + (threadIdx.x >> 5);
    if (node >= N_NODES) return;
    int lane = threadIdx.x & 31;
    constexpr int V = D / 128;

    float4 acc[V];
    const float4* rp = (const float4*)(h + (size_t)node * D);
#pragma unroll
    for (int v = 0; v < V; v++) acc[v] = rp[lane + 32 * v];

    int beg = off[node], end = off[node + 1];
    int e = beg;
    for (; e + 4 <= end; e += 4) {
        int s0 = csr[e], s1 = csr[e + 1], s2 = csr[e + 2], s3 = csr[e + 3];
        const float4* p0 = (const float4*)(h + (size_t)s0 * D);
        const float4* p1 = (const float4*)(h + (size_t)s1 * D);
        const float4* p2 = (const float4*)(h + (size_t)s2 * D);
        const float4* p3 = (const float4*)(h + (size_t)s3 * D);
#pragma unroll
        for (int v = 0; v < V; v++) {
            float4 t0 = p0[lane + 32 * v];
            float4 t1 = p1[lane + 32 * v];
            float4 t2 = p2[lane + 32 * v];
            float4 t3 = p3[lane + 32 * v];
            acc[v].x += t0.x + t1.x + t2.x + t3.x;
            acc[v].y += t0.y + t1.y + t2.y + t3.y;
            acc[v].z += t0.z + t1.z + t2.z + t3.z;
            acc[v].w += t0.w + t1.w + t2.w + t3.w;
        }
    }
    for (; e < end; e++) {
        int s = csr[e];
        const float4* sp = (const float4*)(h + (size_t)s * D);
#pragma unroll
        for (int v = 0; v < V; v++) {
            float4 t = sp[lane + 32 * v];
            acc[v].x += t.x; acc[v].y += t.y; acc[v].z += t.z; acc[v].w += t.w;
        }
    }
    float4* op = (float4*)(out + (size_t)node * D);
#pragma unroll
    for (int v = 0; v < V; v++) op[lane + 32 * v] = acc[v];
}

// ---------------- bf16-split tensor-core GEMM (~fp32 precision) -------------
// Full-width tile: 128 rows x 256 cols per CTA, 512 threads (16 warps, 4m x 4n).
// a*b ~= ahi*bhi + ahi*blo + alo*bhi.  Rows padded to TROW=36 words: frag bank
// = (4g+tg) mod 32 -> conflict-free.
// FUSE=0: C = relu(A@W + bias).  FUSE=1: out = log_softmax(relu(A@W+bias)@w4+b4).
#define MMA_BF16(c, a, b0, b1)                                                  \
    asm volatile(                                                               \
        "mma.sync.aligned.m16n8k16.row.col.f32.bf16.bf16.f32 "                 \
        "{%0,%1,%2,%3}, {%4,%5,%6,%7}, {%8,%9}, {%0,%1,%2,%3};"                \
        : "+f"(c[0]), "+f"(c[1]), "+f"(c[2]), "+f"(c[3])                        \
        : "r"(a[0]), "r"(a[1]), "r"(a[2]), "r"(a[3]), "r"(b0), "r"(b1))

#define TROW 36
#define SMEM_BF ((2 * 128 * TROW + 2 * 256 * TROW) * 4)   // 110592 B

template <int K, int FUSE>
__global__ void __launch_bounds__(512, 1)
sgemm_bf16(const float* __restrict__ A, const __nv_bfloat16* __restrict__ Whi,
           const __nv_bfloat16* __restrict__ Wlo, const float* __restrict__ bias,
           float* __restrict__ C, const float* __restrict__ w4,
           const float* __restrict__ b4, int M) {
    extern __shared__ uint32_t smw[];
    uint32_t* Ah = smw;                 // [128][TROW]
    uint32_t* Al = Ah + 128 * TROW;
    uint32_t* Bh = Al + 128 * TROW;     // [256][TROW]
    uint32_t* Bl = Bh + 256 * TROW;

    const int rb = blockIdx.x * 128;
    int tid = threadIdx.x, wid = tid >> 5, lane = tid & 31;
    int wm = wid & 3, wn = wid >> 2;
    int g = lane >> 2, tg = lane & 3;

    float acc[2][8][4];
#pragma unroll
    for (int mt = 0; mt < 2; mt++)
#pragma unroll
        for (int nt = 0; nt < 8; nt++)
#pragma unroll
            for (int q = 0; q < 4; q++) acc[mt][nt][q] = 0.0f;

    for (int kc = 0; kc < K; kc += 64) {
        __syncthreads();
        // A chunk: 128 rows x 64 f32 -> bf16 hi/lo (4 iters x 512 thr)
#pragma unroll
        for (int it = 0; it < 4; it++) {
            int idx = it * 512 + tid;          // 0..2047
            int r = idx >> 4, gp = idx & 15;
            int rr = min(rb + r, M - 1);
            float4 v = ((const float4*)(A + (size_t)rr * K + kc))[gp];
            float f[4] = {v.x, v.y, v.z, v.w};
            __nv_bfloat16 hi4[4], lo4[4];
#pragma unroll
            for (int q = 0; q < 4; q++) {
                hi4[q] = __float2bfloat16(f[q]);
                lo4[q] = __float2bfloat16(f[q] - __bfloat162float(hi4[q]));
            }
            *(uint2*)(Ah + r * TROW + gp * 2) = *(uint2*)hi4;
            *(uint2*)(Al + r * TROW + gp * 2) = *(uint2*)lo4;
        }
        // B chunk: 256 n-rows x 64 k bf16 (4 iters x 512 thr)
#pragma unroll
        for (int it = 0; it < 4; it++) {
            int idx = it * 512 + tid;          // 0..2047
            int n = idx >> 3, gp = idx & 7;
            uint4 vh = *(const uint4*)(Whi + (size_t)n * K + kc + gp * 8);
            uint4 vl = *(const uint4*)(Wlo + (size_t)n * K + kc + gp * 8);
            *(uint4*)(Bh + n * TROW + gp * 4) = vh;
            *(uint4*)(Bl + n * TROW + gp * 4) = vl;
        }
        __syncthreads();

#pragma unroll
        for (int s = 0; s < 4; s++) {
            uint32_t ah[2][4], al[2][4];
#pragma unroll
            for (int mt = 0; mt < 2; mt++) {
                int base = (wm * 32 + mt * 16 + g) * TROW + s * 8 + tg;
                ah[mt][0] = Ah[base];
                ah[mt][1] = Ah[base + 8 * TROW];
                ah[mt][2] = Ah[base + 4];
                ah[mt][3] = Ah[base + 8 * TROW + 4];
                al[mt][0] = Al[base];
                al[mt][1] = Al[base + 8 * TROW];
                al[mt][2] = Al[base + 4];
                al[mt][3] = Al[base + 8 * TROW + 4];
            }
#pragma unroll
            for (int nt = 0; nt < 8; nt++) {
                int wb = (wn * 64 + nt * 8 + g) * TROW + s * 8 + tg;
                uint32_t bh0 = Bh[wb], bh1 = Bh[wb + 4];
                uint32_t bl0 = Bl[wb], bl1 = Bl[wb + 4];
#pragma unroll
                for (int mt = 0; mt < 2; mt++) {
                    MMA_BF16(acc[mt][nt], ah[mt], bh0, bh1);
                    MMA_BF16(acc[mt][nt], ah[mt], bl0, bl1);
                    MMA_BF16(acc[mt][nt], al[mt], bh0, bh1);
                }
            }
        }
    }

    if (!FUSE) {
        // epilogue: bias + relu, float2 stores (full 256 cols per CTA)
#pragma unroll
        for (int mt = 0; mt < 2; mt++) {
            int row0 = rb + wm * 32 + mt * 16 + g;
#pragma unroll
            for (int nt = 0; nt < 8; nt++) {
                int col = wn * 64 + nt * 8 + 2 * tg;
                float b0 = bias[col], b1 = bias[col + 1];
                if (row0 < M) {
                    float2 o;
                    o.x = fmaxf(acc[mt][nt][0] + b0, 0.0f);
                    o.y = fmaxf(acc[mt][nt][1] + b1, 0.0f);
                    *(float2*)(C + (size_t)row0 * 256 + col) = o;
                }
                if (row0 + 8 < M) {
                    float2 o;
                    o.x = fmaxf(acc[mt][nt][2] + b0, 0.0f);
                    o.y = fmaxf(acc[mt][nt][3] + b1, 0.0f);
                    *(float2*)(C + (size_t)(row0 + 8) * 256 + col) = o;
                }
            }
        }
    } else {
        // fused: h = relu(acc+bias); z = h @ w4[256x2]; log_softmax; never write h.
        float z0p[4] = {0, 0, 0, 0}, z1p[4] = {0, 0, 0, 0};
#pragma unroll
        for (int mt = 0; mt < 2; mt++) {
#pragma unroll
            for (int nt = 0; nt < 8; nt++) {
                int col = wn * 64 + nt * 8 + 2 * tg;
                float b0 = bias[col], b1 = bias[col + 1];
                float w40a = w4[col * 2],       w41a = w4[col * 2 + 1];
                float w40b = w4[(col + 1) * 2], w41b = w4[(col + 1) * 2 + 1];
                float h00 = fmaxf(acc[mt][nt][0] + b0, 0.0f);
                float h01 = fmaxf(acc[mt][nt][1] + b1, 0.0f);
                float h10 = fmaxf(acc[mt][nt][2] + b0, 0.0f);
                float h11 = fmaxf(acc[mt][nt][3] + b1, 0.0f);
                z0p[mt * 2 + 0] += h00 * w40a + h01 * w40b;
                z1p[mt * 2 + 0] += h00 * w41a + h01 * w41b;
                z0p[mt * 2 + 1] += h10 * w40a + h11 * w40b;
                z1p[mt * 2 + 1] += h10 * w41a + h11 * w41b;
            }
        }
        // reduce over tg (lane low 2 bits)
#pragma unroll
        for (int d = 1; d <= 2; d <<= 1) {
#pragma unroll
            for (int q = 0; q < 4; q++) {
                z0p[q] += __shfl_xor_sync(0xFFFFFFFFu, z0p[q], d);
                z1p[q] += __shfl_xor_sync(0xFFFFFFFFu, z1p[q], d);
            }
        }
        __syncthreads();                 // all MMA-phase smem reads done
        float* zs = (float*)smw;         // reuse: [128][2]
        if (tid < 256) zs[tid] = 0.0f;
        __syncthreads();
        if (tg == 0) {
#pragma unroll
            for (int q = 0; q < 4; q++) {
                int rloc = wm * 32 + (q >> 1) * 16 + (q & 1) * 8 + g;
                atomicAdd(&zs[rloc * 2 + 0], z0p[q]);
                atomicAdd(&zs[rloc * 2 + 1], z1p[q]);
            }
        }
        __syncthreads();
        if (tid < 128) {
            int row = rb + tid;
            if (row < M) {
                float z0 = zs[tid * 2 + 0] + b4[0];
                float z1 = zs[tid * 2 + 1] + b4[1];
                float m = fmaxf(z0, z1);
                float l = m + logf(expf(z0 - m) + expf(z1 - m));
                C[row * 2 + 0] = z0 - l;
                C[row * 2 + 1] = z1 - l;
            }
        }
    }
}

// ---------------- launcher --------------------------------------------------
extern "C" void kernel_launch(void* const* d_in, const int* in_sizes, int n_in,
                              void* d_out, int out_size) {
    const float* x    = (const float*)d_in[0];
    const int*   ei32 = (const int*)d_in[1];
    const float* w1 = (const float*)d_in[2]; const float* b1 = (const float*)d_in[3];
    const float* w2 = (const float*)d_in[4]; const float* b2 = (const float*)d_in[5];
    const float* w3 = (const float*)d_in[6]; const float* b3 = (const float*)d_in[7];
    const float* w4 = (const float*)d_in[8]; const float* b4 = (const float*)d_in[9];
    float* out = (float*)d_out;

    static int *deg, *off, *cur, *csr, *bsum;
    static float *h0, *h1, *h2, *h3;
    static __nv_bfloat16 *w1hi, *w1lo, *w2hi, *w2lo, *w3hi, *w3lo;
    static bool init_done = false;
    if (!init_done) {
        cudaGetSymbolAddress((void**)&deg, g_deg);
        cudaGetSymbolAddress((void**)&off, g_off);
        cudaGetSymbolAddress((void**)&cur, g_cur);
        cudaGetSymbolAddress((void**)&csr, g_csr);
        cudaGetSymbolAddress((void**)&bsum, g_bsum);
        cudaGetSymbolAddress((void**)&h0, g_h0);
        cudaGetSymbolAddress((void**)&h1, g_h1);
        cudaGetSymbolAddress((void**)&h2, g_h2);
        cudaGetSymbolAddress((void**)&h3, g_h3);
        cudaGetSymbolAddress((void**)&w1hi, g_w1hi);
        cudaGetSymbolAddress((void**)&w1lo, g_w1lo);
        cudaGetSymbolAddress((void**)&w2hi, g_w2hi);
        cudaGetSymbolAddress((void**)&w2lo, g_w2lo);
        cudaGetSymbolAddress((void**)&w3hi, g_w3hi);
        cudaGetSymbolAddress((void**)&w3lo, g_w3lo);
        cudaFuncSetAttribute(sgemm_bf16<128, 0>,
                             cudaFuncAttributeMaxDynamicSharedMemorySize, SMEM_BF);
        cudaFuncSetAttribute(sgemm_bf16<256, 0>,
                             cudaFuncAttributeMaxDynamicSharedMemorySize, SMEM_BF);
        cudaFuncSetAttribute(sgemm_bf16<256, 1>,
                             cudaFuncAttributeMaxDynamicSharedMemorySize, SMEM_BF);
        init_done = true;
    }

    const int EB = (N_EDGES + 255) / 256;
    const int NB = (N_NODES + 255) / 256;
    const int GB = (N_NODES + 7) / 8;
    const int TCG = (N_NODES + 127) / 128;   // 391

    // prep: zero degrees + all weight splits in one launch
    prep_kernel<<<640, 256>>>(w1, w2, w3, w1hi, w1lo, w2hi, w2lo, w3hi, w3lo, deg);

    // CSR build
    hist_kernel<<<EB, 256>>>(ei32, deg);
    scan1_kernel<<<SCAN_BLKS, 256>>>(deg, off, bsum);
    scan2_kernel<<<1, 256>>>(bsum);
    scan3_kernel<<<NB, 256>>>(off, bsum, cur);
    fill_kernel<<<EB, 256>>>(ei32, cur, csr);

    // layer 1: h0 = x + agg(x); h1 = relu(h0@w1+b1); h2 = relu(h1@w2+b2)
    gather_kernel<128><<<GB, 256>>>(x, csr, off, h0);
    sgemm_bf16<128, 0><<<TCG, 512, SMEM_BF>>>(h0, w1hi, w1lo, b1, h1, w4, b4, N_NODES);
    sgemm_bf16<256, 0><<<TCG, 512, SMEM_BF>>>(h1, w2hi, w2lo, b2, h2, w4, b4, N_NODES);

    // layer 2: h3 = h2 + agg(h2); out = log_softmax(relu(h3@w3+b3)@w4+b4)
    gather_kernel<256><<<GB, 256>>>(h2, csr, off, h3);
    sgemm_bf16<256, 1><<<TCG, 512, SMEM_BF>>>(h3, w3hi, w3lo, b3, out, w4, b4, N_NODES);
}

// round 17
// speedup vs baseline: 2.8317x; 1.0013x over previous
#include <cuda_runtime.h>
#include <cuda_bf16.h>
#include <math.h>
#include <stdint.h>

#define N_NODES 50000
#define N_EDGES 600000
#define D_IN    128
#define D_H     256
#define SCAN_BLKS ((N_NODES + 255) / 256)   // 196

// ---------------- static device scratch (no allocations allowed) ------------
__device__ int   g_deg[N_NODES];
__device__ int   g_off[N_NODES + 1];
__device__ int   g_cur[N_NODES];
__device__ int   g_bsum[SCAN_BLKS];
__device__ int   g_csr[N_EDGES];
__device__ float g_h0[(size_t)N_NODES * D_IN];
__device__ float g_h1[(size_t)N_NODES * D_H];
__device__ float g_h2[(size_t)N_NODES * D_H];
__device__ float g_h3[(size_t)N_NODES * D_H];
// transposed bf16 hi/lo split weights: Wt[n][k] = W[k][n]
__device__ __align__(16) __nv_bfloat16 g_w1hi[D_H * D_IN], g_w1lo[D_H * D_IN];
__device__ __align__(16) __nv_bfloat16 g_w2hi[D_H * D_H],  g_w2lo[D_H * D_H];
__device__ __align__(16) __nv_bfloat16 g_w3hi[D_H * D_H],  g_w3lo[D_H * D_H];

// ---------------- per-block edge dtype detection -----------------------------
__device__ __forceinline__ int block_detect_is64(const int* __restrict__ ei32) {
    __shared__ int s_is64;
    if (threadIdx.x == 0) {
        int az = 1;
#pragma unroll
        for (int i = 0; i < 8; i++)
            if (ei32[2 * i + 1] != 0) { az = 0; break; }
        s_is64 = az;
    }
    __syncthreads();
    return s_is64;
}
__device__ __forceinline__ int edge_src(const int* ei32, int is64, int i) {
    return is64 ? ei32[2 * i] : ei32[i];
}
__device__ __forceinline__ int edge_dst(const int* ei32, int is64, int i) {
    return is64 ? ei32[2 * N_EDGES + 2 * i] : ei32[N_EDGES + i];
}

// ---------------- prep: zero degrees + transpose/split all weights ----------
__global__ void prep_kernel(const float* __restrict__ w1, const float* __restrict__ w2,
                            const float* __restrict__ w3,
                            __nv_bfloat16* __restrict__ w1hi, __nv_bfloat16* __restrict__ w1lo,
                            __nv_bfloat16* __restrict__ w2hi, __nv_bfloat16* __restrict__ w2lo,
                            __nv_bfloat16* __restrict__ w3hi, __nv_bfloat16* __restrict__ w3lo,
                            int* __restrict__ deg) {
    int i = blockIdx.x * blockDim.x + threadIdx.x;
    if (i < N_NODES) deg[i] = 0;

    const float* w; __nv_bfloat16 *hi, *lo; int j, K;
    if (i < 32768)       { w = w1; hi = w1hi; lo = w1lo; j = i;          K = D_IN; }
    else if (i < 98304)  { w = w2; hi = w2hi; lo = w2lo; j = i - 32768;  K = D_H; }
    else if (i < 163840) { w = w3; hi = w3hi; lo = w3lo; j = i - 98304;  K = D_H; }
    else return;
    int k = j >> 8, n = j & 255;
    float x = w[j];
    __nv_bfloat16 h = __float2bfloat16(x);
    float r = x - __bfloat162float(h);
    hi[(size_t)n * K + k] = h;
    lo[(size_t)n * K + k] = __float2bfloat16(r);
}

// ---------------- CSR build -------------------------------------------------
__global__ void hist_kernel(const int* __restrict__ ei32, int* __restrict__ deg) {
    int is64 = block_detect_is64(ei32);
    int i = blockIdx.x * blockDim.x + threadIdx.x;
    if (i < N_EDGES) atomicAdd(&deg[edge_dst(ei32, is64, i)], 1);
}
__global__ void scan1_kernel(const int* __restrict__ deg, int* __restrict__ off,
                             int* __restrict__ bsum) {
    __shared__ int sd[256];
    int tid = threadIdx.x;
    int i = blockIdx.x * 256 + tid;
    int v = (i < N_NODES) ? deg[i] : 0;
    sd[tid] = v;
    __syncthreads();
    for (int d = 1; d < 256; d <<= 1) {
        int t = (tid >= d) ? sd[tid - d] : 0;
        __syncthreads();
        sd[tid] += t;
        __syncthreads();
    }
    if (i < N_NODES) off[i] = sd[tid] - v;
    if (tid == 255) bsum[blockIdx.x] = sd[255];
}
// scan3 (merged with old scan2): block b adds prefix = sum(bsum[0..b))
__global__ void scan3_kernel(int* __restrict__ off, const int* __restrict__ bsum,
                             int* __restrict__ cur) {
    __shared__ int sred[256];
    int tid = threadIdx.x;
    int b = blockIdx.x;
    int partial = 0;
    for (int j = tid; j < b; j += 256) partial += bsum[j];
    sred[tid] = partial;
    __syncthreads();
    for (int d = 128; d > 0; d >>= 1) {
        if (tid < d) sred[tid] += sred[tid + d];
        __syncthreads();
    }
    int pre = sred[0];
    int i = b * 256 + tid;
    if (i < N_NODES) {
        int o = off[i] + pre;
        off[i] = o;
        cur[i] = o;
    }
    if (i == 0) off[N_NODES] = N_EDGES;
}
__global__ void fill_kernel(const int* __restrict__ ei32,
                            int* __restrict__ cur, int* __restrict__ csr) {
    int is64 = block_detect_is64(ei32);
    int i = blockIdx.x * blockDim.x + threadIdx.x;
    if (i < N_EDGES) {
        int p = atomicAdd(&cur[edge_dst(ei32, is64, i)], 1);
        csr[p] = edge_src(ei32, is64, i);
    }
}

// ---------------- gather aggregation: out[i] = h[i] + sum_{j->i} h[j] -------
template <int D, int U>
__global__ void gather_kernel(const float* __restrict__ h, const int* __restrict__ csr,
                              const int* __restrict__ off, float* __restrict__ out) {
    int node = blockIdx.x * (blockDim.x / 32) + (threadIdx.x >> 5);
    if (node >= N_NODES) return;
    int lane = threadIdx.x & 31;
    constexpr int V = D / 128;

    float4 acc[V];
    const float4* rp = (const float4*)(h + (size_t)node * D);
#pragma unroll
    for (int v = 0; v < V; v++) acc[v] = rp[lane + 32 * v];

    int beg = off[node], end = off[node + 1];
    int e = beg;
    for (; e + U <= end; e += U) {
        int s[U];
#pragma unroll
        for (int u = 0; u < U; u++) s[u] = csr[e + u];
#pragma unroll
        for (int v = 0; v < V; v++) {
            float4 t[U];
#pragma unroll
            for (int u = 0; u < U; u++)
                t[u] = ((const float4*)(h + (size_t)s[u] * D))[lane + 32 * v];
#pragma unroll
            for (int u = 0; u < U; u++) {
                acc[v].x += t[u].x; acc[v].y += t[u].y;
                acc[v].z += t[u].z; acc[v].w += t[u].w;
            }
        }
    }
    for (; e < end; e++) {
        int s = csr[e];
        const float4* sp = (const float4*)(h + (size_t)s * D);
#pragma unroll
        for (int v = 0; v < V; v++) {
            float4 t = sp[lane + 32 * v];
            acc[v].x += t.x; acc[v].y += t.y; acc[v].z += t.z; acc[v].w += t.w;
        }
    }
    float4* op = (float4*)(out + (size_t)node * D);
#pragma unroll
    for (int v = 0; v < V; v++) op[lane + 32 * v] = acc[v];
}

// ---------------- bf16-split tensor-core GEMM (~fp32 precision) -------------
// 128 rows x 256 cols per CTA, 256 threads = 8 warps (2m x 4n), warp tile 64x64.
// Crossbar traffic: A x4(wn) + B x2(wm) = 256KB / 64-chunk (was 384KB at 4x4).
// a*b ~= ahi*bhi + ahi*blo + alo*bhi.  TROW=36 pad: frag bank (4g+tg), conflict-free.
#define MMA_BF16(c, a, b0, b1)                                                  \
    asm volatile(                                                               \
        "mma.sync.aligned.m16n8k16.row.col.f32.bf16.bf16.f32 "                 \
        "{%0,%1,%2,%3}, {%4,%5,%6,%7}, {%8,%9}, {%0,%1,%2,%3};"                \
        : "+f"(c[0]), "+f"(c[1]), "+f"(c[2]), "+f"(c[3])                        \
        : "r"(a[0]), "r"(a[1]), "r"(a[2]), "r"(a[3]), "r"(b0), "r"(b1))

#define TROW 36
#define SMEM_BF ((2 * 128 * TROW + 2 * 256 * TROW) * 4)   // 110592 B

template <int K, int FUSE>
__global__ void __launch_bounds__(256, 1)
sgemm_bf16(const float* __restrict__ A, const __nv_bfloat16* __restrict__ Whi,
           const __nv_bfloat16* __restrict__ Wlo, const float* __restrict__ bias,
           float* __restrict__ C, const float* __restrict__ w4,
           const float* __restrict__ b4, int M) {
    extern __shared__ uint32_t smw[];
    uint32_t* Ah = smw;                 // [128][TROW]
    uint32_t* Al = Ah + 128 * TROW;
    uint32_t* Bh = Al + 128 * TROW;     // [256][TROW]
    uint32_t* Bl = Bh + 256 * TROW;

    const int rb = blockIdx.x * 128;
    int tid = threadIdx.x, wid = tid >> 5, lane = tid & 31;
    int wm = wid & 1, wn = wid >> 1;        // 2m x 4n
    int g = lane >> 2, tg = lane & 3;

    float acc[4][8][4];
#pragma unroll
    for (int mt = 0; mt < 4; mt++)
#pragma unroll
        for (int nt = 0; nt < 8; nt++)
#pragma unroll
            for (int q = 0; q < 4; q++) acc[mt][nt][q] = 0.0f;

    for (int kc = 0; kc < K; kc += 64) {
        __syncthreads();
        // A chunk: 128 rows x 64 f32 -> bf16 hi/lo (8 iters x 256 thr)
#pragma unroll
        for (int it = 0; it < 8; it++) {
            int idx = it * 256 + tid;          // 0..2047
            int r = idx >> 4, gp = idx & 15;
            int rr = min(rb + r, M - 1);
            float4 v = ((const float4*)(A + (size_t)rr * K + kc))[gp];
            float f[4] = {v.x, v.y, v.z, v.w};
            __nv_bfloat16 hi4[4], lo4[4];
#pragma unroll
            for (int q = 0; q < 4; q++) {
                hi4[q] = __float2bfloat16(f[q]);
                lo4[q] = __float2bfloat16(f[q] - __bfloat162float(hi4[q]));
            }
            *(uint2*)(Ah + r * TROW + gp * 2) = *(uint2*)hi4;
            *(uint2*)(Al + r * TROW + gp * 2) = *(uint2*)lo4;
        }
        // B chunk: 256 n-rows x 64 k bf16 (8 iters x 256 thr)
#pragma unroll
        for (int it = 0; it < 8; it++) {
            int idx = it * 256 + tid;          // 0..2047
            int n = idx >> 3, gp = idx & 7;
            uint4 vh = *(const uint4*)(Whi + (size_t)n * K + kc + gp * 8);
            uint4 vl = *(const uint4*)(Wlo + (size_t)n * K + kc + gp * 8);
            *(uint4*)(Bh + n * TROW + gp * 4) = vh;
            *(uint4*)(Bl + n * TROW + gp * 4) = vl;
        }
        __syncthreads();

#pragma unroll
        for (int s = 0; s < 4; s++) {
            uint32_t ah[4][4], al[4][4];
#pragma unroll
            for (int mt = 0; mt < 4; mt++) {
                int base = (wm * 64 + mt * 16 + g) * TROW + s * 8 + tg;
                ah[mt][0] = Ah[base];
                ah[mt][1] = Ah[base + 8 * TROW];
                ah[mt][2] = Ah[base + 4];
                ah[mt][3] = Ah[base + 8 * TROW + 4];
                al[mt][0] = Al[base];
                al[mt][1] = Al[base + 8 * TROW];
                al[mt][2] = Al[base + 4];
                al[mt][3] = Al[base + 8 * TROW + 4];
            }
#pragma unroll
            for (int nt = 0; nt < 8; nt++) {
                int wb = (wn * 64 + nt * 8 + g) * TROW + s * 8 + tg;
                uint32_t bh0 = Bh[wb], bh1 = Bh[wb + 4];
                uint32_t bl0 = Bl[wb], bl1 = Bl[wb + 4];
#pragma unroll
                for (int mt = 0; mt < 4; mt++) {
                    MMA_BF16(acc[mt][nt], ah[mt], bh0, bh1);
                    MMA_BF16(acc[mt][nt], ah[mt], bl0, bl1);
                    MMA_BF16(acc[mt][nt], al[mt], bh0, bh1);
                }
            }
        }
    }

    if (!FUSE) {
#pragma unroll
        for (int mt = 0; mt < 4; mt++) {
            int row0 = rb + wm * 64 + mt * 16 + g;
#pragma unroll
            for (int nt = 0; nt < 8; nt++) {
                int col = wn * 64 + nt * 8 + 2 * tg;
                float b0 = bias[col], b1 = bias[col + 1];
                if (row0 < M) {
                    float2 o;
                    o.x = fmaxf(acc[mt][nt][0] + b0, 0.0f);
                    o.y = fmaxf(acc[mt][nt][1] + b1, 0.0f);
                    *(float2*)(C + (size_t)row0 * 256 + col) = o;
                }
                if (row0 + 8 < M) {
                    float2 o;
                    o.x = fmaxf(acc[mt][nt][2] + b0, 0.0f);
                    o.y = fmaxf(acc[mt][nt][3] + b1, 0.0f);
                    *(float2*)(C + (size_t)(row0 + 8) * 256 + col) = o;
                }
            }
        }
    } else {
        // fused: h = relu(acc+bias); z = h @ w4[256x2]; log_softmax; never write h.
        float z0p[8], z1p[8];
#pragma unroll
        for (int q = 0; q < 8; q++) { z0p[q] = 0.0f; z1p[q] = 0.0f; }
#pragma unroll
        for (int mt = 0; mt < 4; mt++) {
#pragma unroll
            for (int nt = 0; nt < 8; nt++) {
                int col = wn * 64 + nt * 8 + 2 * tg;
                float b0 = bias[col], b1 = bias[col + 1];
                float w40a = w4[col * 2],       w41a = w4[col * 2 + 1];
                float w40b = w4[(col + 1) * 2], w41b = w4[(col + 1) * 2 + 1];
                float h00 = fmaxf(acc[mt][nt][0] + b0, 0.0f);
                float h01 = fmaxf(acc[mt][nt][1] + b1, 0.0f);
                float h10 = fmaxf(acc[mt][nt][2] + b0, 0.0f);
                float h11 = fmaxf(acc[mt][nt][3] + b1, 0.0f);
                z0p[mt * 2 + 0] += h00 * w40a + h01 * w40b;
                z1p[mt * 2 + 0] += h00 * w41a + h01 * w41b;
                z0p[mt * 2 + 1] += h10 * w40a + h11 * w40b;
                z1p[mt * 2 + 1] += h10 * w41a + h11 * w41b;
            }
        }
#pragma unroll
        for (int d = 1; d <= 2; d <<= 1) {
#pragma unroll
            for (int q = 0; q < 8; q++) {
                z0p[q] += __shfl_xor_sync(0xFFFFFFFFu, z0p[q], d);
                z1p[q] += __shfl_xor_sync(0xFFFFFFFFu, z1p[q], d);
            }
        }
        __syncthreads();
        float* zs = (float*)smw;         // [128][2]
        zs[tid] = 0.0f;                  // 256 threads cover all 256 slots
        __syncthreads();
        if (tg == 0) {
#pragma unroll
            for (int q = 0; q < 8; q++) {
                int rloc = wm * 64 + (q >> 1) * 16 + (q & 1) * 8 + g;
                atomicAdd(&zs[rloc * 2 + 0], z0p[q]);
                atomicAdd(&zs[rloc * 2 + 1], z1p[q]);
            }
        }
        __syncthreads();
        if (tid < 128) {
            int row = rb + tid;
            if (row < M) {
                float z0 = zs[tid * 2 + 0] + b4[0];
                float z1 = zs[tid * 2 + 1] + b4[1];
                float m = fmaxf(z0, z1);
                float l = m + logf(expf(z0 - m) + expf(z1 - m));
                C[row * 2 + 0] = z0 - l;
                C[row * 2 + 1] = z1 - l;
            }
        }
    }
}

// ---------------- launcher --------------------------------------------------
extern "C" void kernel_launch(void* const* d_in, const int* in_sizes, int n_in,
                              void* d_out, int out_size) {
    const float* x    = (const float*)d_in[0];
    const int*   ei32 = (const int*)d_in[1];
    const float* w1 = (const float*)d_in[2]; const float* b1 = (const float*)d_in[3];
    const float* w2 = (const float*)d_in[4]; const float* b2 = (const float*)d_in[5];
    const float* w3 = (const float*)d_in[6]; const float* b3 = (const float*)d_in[7];
    const float* w4 = (const float*)d_in[8]; const float* b4 = (const float*)d_in[9];
    float* out = (float*)d_out;

    static int *deg, *off, *cur, *csr, *bsum;
    static float *h0, *h1, *h2, *h3;
    static __nv_bfloat16 *w1hi, *w1lo, *w2hi, *w2lo, *w3hi, *w3lo;
    static bool init_done = false;
    if (!init_done) {
        cudaGetSymbolAddress((void**)&deg, g_deg);
        cudaGetSymbolAddress((void**)&off, g_off);
        cudaGetSymbolAddress((void**)&cur, g_cur);
        cudaGetSymbolAddress((void**)&csr, g_csr);
        cudaGetSymbolAddress((void**)&bsum, g_bsum);
        cudaGetSymbolAddress((void**)&h0, g_h0);
        cudaGetSymbolAddress((void**)&h1, g_h1);
        cudaGetSymbolAddress((void**)&h2, g_h2);
        cudaGetSymbolAddress((void**)&h3, g_h3);
        cudaGetSymbolAddress((void**)&w1hi, g_w1hi);
        cudaGetSymbolAddress((void**)&w1lo, g_w1lo);
        cudaGetSymbolAddress((void**)&w2hi, g_w2hi);
        cudaGetSymbolAddress((void**)&w2lo, g_w2lo);
        cudaGetSymbolAddress((void**)&w3hi, g_w3hi);
        cudaGetSymbolAddress((void**)&w3lo, g_w3lo);
        cudaFuncSetAttribute(sgemm_bf16<128, 0>,
                             cudaFuncAttributeMaxDynamicSharedMemorySize, SMEM_BF);
        cudaFuncSetAttribute(sgemm_bf16<256, 0>,
                             cudaFuncAttributeMaxDynamicSharedMemorySize, SMEM_BF);
        cudaFuncSetAttribute(sgemm_bf16<256, 1>,
                             cudaFuncAttributeMaxDynamicSharedMemorySize, SMEM_BF);
        init_done = true;
    }

    const int EB = (N_EDGES + 255) / 256;
    const int GB = (N_NODES + 7) / 8;
    const int TCG = (N_NODES + 127) / 128;   // 391

    // prep: zero degrees + all weight splits in one launch
    prep_kernel<<<640, 256>>>(w1, w2, w3, w1hi, w1lo, w2hi, w2lo, w3hi, w3lo, deg);

    // CSR build (scan2 merged into scan3)
    hist_kernel<<<EB, 256>>>(ei32, deg);
    scan1_kernel<<<SCAN_BLKS, 256>>>(deg, off, bsum);
    scan3_kernel<<<SCAN_BLKS, 256>>>(off, bsum, cur);
    fill_kernel<<<EB, 256>>>(ei32, cur, csr);

    // layer 1: h0 = x + agg(x); h1 = relu(h0@w1+b1); h2 = relu(h1@w2+b2)
    gather_kernel<128, 8><<<GB, 256>>>(x, csr, off, h0);
    sgemm_bf16<128, 0><<<TCG, 256, SMEM_BF>>>(h0, w1hi, w1lo, b1, h1, w4, b4, N_NODES);
    sgemm_bf16<256, 0><<<TCG, 256, SMEM_BF>>>(h1, w2hi, w2lo, b2, h2, w4, b4, N_NODES);

    // layer 2: h3 = h2 + agg(h2); out = log_softmax(relu(h3@w3+b3)@w4+b4)
    gather_kernel<256, 4><<<GB, 256>>>(h2, csr, off, h3);
    sgemm_bf16<256, 1><<<TCG, 256, SMEM_BF>>>(h3, w3hi, w3lo, b3, out, w4, b4, N_NODES);
}